// round 7
// baseline (speedup 1.0000x reference)
#include <cuda_runtime.h>
#include <cuda_bf16.h>

#define NTHREADS 256
#define MINBLK   6
#define NBLOCKS  (148 * MINBLK)
#define LVL      64

// Quantize/dequantize (AdaptedEntropyModel):
//   r = x - means
//   pos = clip(searchsorted(cb, r, side='left'), 1, 63)
//   sym = (r - cb[pos-1] <= cb[pos] - r) ? pos-1 : pos
//   y_hat = cb[sym] + means
// Output (out_size == 2N floats): [0..N) = float(sym), [N..2N) = y_hat.
//
// R6 = R5 (2-stage reg pipeline, cheap search body) +
//   (a) prefetch.global.L2 two iterations ahead on both input streams
//       (raises per-warp MLP with zero register cost; pipelined LDG then
//        hits L2 instead of DRAM), and
//   (b) level-16 probe hoisted to registers (cb15/cb47 select): 6 LDS/elem
//       instead of 7, one FSETP+SEL per element.

__device__ __forceinline__ void process4(float4 xv, float4 mv,
                                         const float* __restrict__ mycb,
                                         float cb31, float cb15, float cb47,
                                         float4& so, float4& yo)
{
    float r[4]  = { xv.x - mv.x, xv.y - mv.y, xv.z - mv.z, xv.w - mv.w };
    float mn[4] = { mv.x, mv.y, mv.z, mv.w };
    float sy[4], yy[4];

    #pragma unroll
    for (int j = 0; j < 4; ++j) {
        const float rv = r[j];
        // Branchless lower_bound over 64 sorted entries (6 steps);
        // levels 32 and 16 probe registers, levels 8..1 probe shared.
        bool  t1  = (cb31 < rv);
        int   pos = t1 ? 32 : 0;
        float p16 = t1 ? cb47 : cb15;
        if (p16 < rv) pos += 16;
        #pragma unroll
        for (int step = 8; step > 0; step >>= 1) {
            if (mycb[(pos + step - 1) << 5] < rv) pos += step;
        }
        pos = min(max(pos, 1), LVL - 1);       // clip to [1,63] like reference
        float left  = mycb[(pos - 1) << 5];
        float right = mycb[pos << 5];
        // Exact tie rule from the reference, same fp32 ops.
        bool take_left = (rv - left) <= (right - rv);
        sy[j] = (float)(take_left ? (pos - 1) : pos);
        yy[j] = (take_left ? left : right) + mn[j];
    }
    so = make_float4(sy[0], sy[1], sy[2], sy[3]);
    yo = make_float4(yy[0], yy[1], yy[2], yy[3]);
}

__global__ void __launch_bounds__(NTHREADS, MINBLK)
quant_dequant_kernel(const float4* __restrict__ x4,
                     const float4* __restrict__ m4,
                     const float*  __restrict__ cb,
                     float* __restrict__ out_sym,
                     float* __restrict__ out_y,
                     int n4, int n)
{
    // Lane-private codebook replicas: entry i for lane l at s_cb[i*32 + l] ->
    // every data-dependent probe hits bank == lane (conflict-free).
    __shared__ float s_cb[LVL * 32];
    for (int i = threadIdx.x; i < LVL * 32; i += NTHREADS)
        s_cb[i] = cb[i >> 5];
    const float cb15 = __ldg(cb + 15);
    const float cb31 = __ldg(cb + 31);
    const float cb47 = __ldg(cb + 47);
    __syncthreads();

    const int    lane = threadIdx.x & 31;
    const float* mycb = s_cb + lane;           // mycb[idx*32] == cb[idx]

    const int stride = gridDim.x * NTHREADS;
    int i = blockIdx.x * NTHREADS + threadIdx.x;

    if (i < n4) {
        // 2-stage register pipeline + L2 prefetch one more stride ahead.
        float4 xv = x4[i];
        float4 mv = m4[i];
        int inext = i + stride;
        while (inext < n4) {
            int ipf = inext + stride;
            if (ipf < n4) {
                asm volatile("prefetch.global.L2 [%0];" :: "l"(x4 + ipf));
                asm volatile("prefetch.global.L2 [%0];" :: "l"(m4 + ipf));
            }
            float4 xn  = x4[inext];
            float4 mn_ = m4[inext];
            float4 so, yo;
            process4(xv, mv, mycb, cb31, cb15, cb47, so, yo);
            ((float4*)out_sym)[i] = so;
            ((float4*)out_y)[i]   = yo;
            i = inext; inext += stride;
            xv = xn; mv = mn_;
        }
        float4 so, yo;
        process4(xv, mv, mycb, cb31, cb15, cb47, so, yo);
        ((float4*)out_sym)[i] = so;
        ((float4*)out_y)[i]   = yo;
    }

    // Scalar tail (n not divisible by 4 — not expected here, but safe).
    int tail_start = n4 * 4;
    for (int t = tail_start + blockIdx.x * NTHREADS + threadIdx.x; t < n; t += stride) {
        const float* xs = (const float*)x4;
        const float* ms = (const float*)m4;
        float mvs = ms[t];
        float rv  = xs[t] - mvs;
        bool  t1  = (cb31 < rv);
        int   pos = t1 ? 32 : 0;
        float p16 = t1 ? cb47 : cb15;
        if (p16 < rv) pos += 16;
        #pragma unroll
        for (int step = 8; step > 0; step >>= 1) {
            if (mycb[(pos + step - 1) << 5] < rv) pos += step;
        }
        pos = min(max(pos, 1), LVL - 1);
        float left  = mycb[(pos - 1) << 5];
        float right = mycb[pos << 5];
        bool take_left = (rv - left) <= (right - rv);
        out_sym[t] = (float)(take_left ? (pos - 1) : pos);
        out_y[t]   = (take_left ? left : right) + mvs;
    }
}

extern "C" void kernel_launch(void* const* d_in, const int* in_sizes, int n_in,
                              void* d_out, int out_size)
{
    const float* x     = (const float*)d_in[0];   // [B,C,H,W] f32
    const float* means = (const float*)d_in[1];   // [B,C,H,W] f32
    const float* cb    = (const float*)d_in[2];   // [64] f32 sorted

    int n  = in_sizes[0];
    int n4 = n >> 2;

    float* out_sym = (float*)d_out;       // first N floats: symbols (exact in f32)
    float* out_y   = out_sym + n;         // next  N floats: y_hat

    quant_dequant_kernel<<<NBLOCKS, NTHREADS>>>(
        (const float4*)x, (const float4*)means, cb, out_sym, out_y, n4, n);
}

// round 9
// speedup vs baseline: 1.0319x; 1.0319x over previous
#include <cuda_runtime.h>
#include <cuda_bf16.h>
#include <cstdint>

#define NTHREADS 256
#define MINBLK   7
#define NBLOCKS  (148 * MINBLK)
#define LVL      64
#define STAGES   3

// Quantize/dequantize (AdaptedEntropyModel):
//   r = x - means
//   pos = clip(searchsorted(cb, r, side='left'), 1, 63)
//   sym = (r - cb[pos-1] <= cb[pos] - r) ? pos-1 : pos
//   y_hat = cb[sym] + means
// Output (out_size == 2N floats): [0..N) = float(sym), [N..2N) = y_hat.
//
// R8 = R7 with the missing <cstdint> include fixed.
// cp.async (LDGSTS) 3-stage pipeline: inputs are copied gmem->smem two
// iterations ahead with zero register cost (.cg path, L2-only), consumed via
// per-thread-private LDS.128 (no block barrier needed: each thread reads only
// its own slots, ordered by cp.async.wait_group). Body stays at the cheap
// R2/R5 search (cb31 register probe + 5 shared probes + 2 neighbor LDS).
// Outputs stored with .cs (evict-first: never re-read).

__device__ __forceinline__ void cp_async16(unsigned int smem_dst, const void* gsrc) {
    asm volatile("cp.async.cg.shared.global [%0], [%1], 16;"
                 :: "r"(smem_dst), "l"(gsrc));
}
__device__ __forceinline__ void cp_commit() {
    asm volatile("cp.async.commit_group;");
}
__device__ __forceinline__ void cp_wait1() {
    asm volatile("cp.async.wait_group 1;");
}
__device__ __forceinline__ void cp_wait0() {
    asm volatile("cp.async.wait_group 0;");
}

__device__ __forceinline__ void process4(float4 xv, float4 mv,
                                         const float* __restrict__ mycb,
                                         float cb31,
                                         float4& so, float4& yo)
{
    float r[4]  = { xv.x - mv.x, xv.y - mv.y, xv.z - mv.z, xv.w - mv.w };
    float mn[4] = { mv.x, mv.y, mv.z, mv.w };
    float sy[4], yy[4];

    #pragma unroll
    for (int j = 0; j < 4; ++j) {
        const float rv = r[j];
        int pos = (cb31 < rv) ? 32 : 0;
        #pragma unroll
        for (int step = 16; step > 0; step >>= 1) {
            if (mycb[(pos + step - 1) << 5] < rv) pos += step;
        }
        pos = min(max(pos, 1), LVL - 1);       // clip to [1,63] like reference
        float left  = mycb[(pos - 1) << 5];
        float right = mycb[pos << 5];
        bool take_left = (rv - left) <= (right - rv);   // exact reference tie rule
        sy[j] = (float)(take_left ? (pos - 1) : pos);
        yy[j] = (take_left ? left : right) + mn[j];
    }
    so = make_float4(sy[0], sy[1], sy[2], sy[3]);
    yo = make_float4(yy[0], yy[1], yy[2], yy[3]);
}

__global__ void __launch_bounds__(NTHREADS, MINBLK)
quant_dequant_kernel(const float4* __restrict__ x4,
                     const float4* __restrict__ m4,
                     const float*  __restrict__ cb,
                     float* __restrict__ out_sym,
                     float* __restrict__ out_y,
                     int n4, int n)
{
    // Lane-private codebook replicas (conflict-free data-dependent probes).
    __shared__ float s_cb[LVL * 32];                    // 8 KB
    __shared__ float4 s_x[STAGES][NTHREADS];            // 12 KB
    __shared__ float4 s_m[STAGES][NTHREADS];            // 12 KB

    for (int i = threadIdx.x; i < LVL * 32; i += NTHREADS)
        s_cb[i] = cb[i >> 5];
    const float cb31 = __ldg(cb + 31);
    __syncthreads();

    const int    tid  = threadIdx.x;
    const int    lane = tid & 31;
    const float* mycb = s_cb + lane;                    // mycb[idx*32] == cb[idx]

    unsigned int sx_base = (unsigned int)__cvta_generic_to_shared(&s_x[0][tid]);
    unsigned int sm_base = (unsigned int)__cvta_generic_to_shared(&s_m[0][tid]);
    const unsigned int stage_bytes = NTHREADS * 16;

    const int stride = gridDim.x * NTHREADS;
    const int i0 = blockIdx.x * NTHREADS + tid;

    // Prologue: launch copies for iterations 0 and 1 (two groups).
    #pragma unroll
    for (int s = 0; s < 2; ++s) {
        int idx = i0 + s * stride;
        if (idx < n4) {
            cp_async16(sx_base + s * stage_bytes, x4 + idx);
            cp_async16(sm_base + s * stage_bytes, m4 + idx);
        }
        cp_commit();
    }

    int i = i0, k = 0;
    while (i < n4) {
        // Complete group k (<=1 group may remain outstanding).
        cp_wait1();
        int buf = k % STAGES;
        float4 xv = s_x[buf][tid];
        float4 mv = s_m[buf][tid];

        // Launch copies for iteration k+2 into buffer (k+2)%STAGES.
        int ipf = i + 2 * stride;
        if (ipf < n4) {
            int nbuf = (k + 2) % STAGES;
            cp_async16(sx_base + nbuf * stage_bytes, x4 + ipf);
            cp_async16(sm_base + nbuf * stage_bytes, m4 + ipf);
        }
        cp_commit();

        float4 so, yo;
        process4(xv, mv, mycb, cb31, so, yo);
        __stcs((float4*)out_sym + i, so);
        __stcs((float4*)out_y   + i, yo);

        i += stride; ++k;
    }
    cp_wait0();   // drain any dangling groups before (possible) tail work

    // Scalar tail (n not divisible by 4 — not expected here, but safe).
    int tail_start = n4 * 4;
    for (int t = tail_start + i0; t < n; t += stride) {
        const float* xs = (const float*)x4;
        const float* ms = (const float*)m4;
        float mvs = ms[t];
        float rv  = xs[t] - mvs;
        int pos = (cb31 < rv) ? 32 : 0;
        #pragma unroll
        for (int step = 16; step > 0; step >>= 1) {
            if (mycb[(pos + step - 1) << 5] < rv) pos += step;
        }
        pos = min(max(pos, 1), LVL - 1);
        float left  = mycb[(pos - 1) << 5];
        float right = mycb[pos << 5];
        bool take_left = (rv - left) <= (right - rv);
        out_sym[t] = (float)(take_left ? (pos - 1) : pos);
        out_y[t]   = (take_left ? left : right) + mvs;
    }
}

extern "C" void kernel_launch(void* const* d_in, const int* in_sizes, int n_in,
                              void* d_out, int out_size)
{
    const float* x     = (const float*)d_in[0];   // [B,C,H,W] f32
    const float* means = (const float*)d_in[1];   // [B,C,H,W] f32
    const float* cb    = (const float*)d_in[2];   // [64] f32 sorted

    int n  = in_sizes[0];
    int n4 = n >> 2;

    float* out_sym = (float*)d_out;       // first N floats: symbols (exact in f32)
    float* out_y   = out_sym + n;         // next  N floats: y_hat

    quant_dequant_kernel<<<NBLOCKS, NTHREADS>>>(
        (const float4*)x, (const float4*)means, cb, out_sym, out_y, n4, n);
}